// round 5
// baseline (speedup 1.0000x reference)
#include <cuda_runtime.h>
#include <cuda_fp16.h>
#include <math.h>

#define NN 4096
#define DIN 256
#define DOUT 256
#define KH 3
#define CAP 384
#define CAPH 192              // per half-row segment
#define GEMM_BLOCKS 768
#define TOTAL_BLOCKS 8960     // 256 groups * 35 (3 gemm + 32 compact)

// scratch (device globals: no allocation allowed)
__device__ float  g_wx[KH * NN * DOUT];          // 12 MB fp32 (for alar)
__device__ __half g_wxh[KH * NN * DOUT];         // 6 MB fp16 (for gather)
__device__ float  g_al[KH * NN * 4];
__device__ float  g_ar[KH * NN * 4];
__device__ unsigned g_list[NN * CAP];            // 6 MB edge lists (2 segs/row)
__device__ int g_cnt[NN * 2];

// ---------------------------------------------------------------------------
// Kernel A: fused GEMM + mask compaction (half-row blocks, front-batched loads)
// ---------------------------------------------------------------------------
__global__ void __launch_bounds__(256)
fused_gemm_compact(const float* __restrict__ x,
                   const float* __restrict__ Wt,
                   const int* __restrict__ supports,
                   const int* __restrict__ atten) {
    __shared__ float As[16][64];
    __shared__ float Bs[16][64];
    __shared__ int s_warp[8];

    int bid = blockIdx.x;               // 0 .. 8959
    int grp = bid / 35;
    int r   = bid % 35;
    int tx  = threadIdx.x;

    if (r < 3) {
        // ---------------- GEMM path ----------------
        int gid = grp * 3 + r;          // 0..767
        int k = gid >> 8;
        int rem = gid & 255;
        int row0 = (rem >> 2) * 64;
        int col0 = (rem & 3) * 64;
        const float* B = Wt + (size_t)k * DIN * DOUT;
        float*  C  = g_wx  + (size_t)k * NN * DOUT;
        __half* Ch = g_wxh + (size_t)k * NN * DOUT;

        int tr = tx >> 4;
        int tc = tx & 15;

        float acc[4][4];
#pragma unroll
        for (int i = 0; i < 4; i++)
#pragma unroll
            for (int j = 0; j < 4; j++) acc[i][j] = 0.f;

        for (int kk = 0; kk < DIN; kk += 16) {
            {
                int rr = tx >> 2;
                int c4 = (tx & 3) * 4;
                float4 v = *(const float4*)(x + (size_t)(row0 + rr) * DIN + kk + c4);
                As[c4 + 0][rr] = v.x;
                As[c4 + 1][rr] = v.y;
                As[c4 + 2][rr] = v.z;
                As[c4 + 3][rr] = v.w;
            }
            {
                int rr = tx >> 4;
                int cc = tx & 15;
                float4 w = *(const float4*)(B + (size_t)(kk + rr) * DOUT + col0 + cc * 4);
                *(float4*)&Bs[rr][cc * 4] = w;
            }
            __syncthreads();
#pragma unroll
            for (int p = 0; p < 16; p++) {
                float4 a = *(float4*)&As[p][tr * 4];
                float4 b = *(float4*)&Bs[p][tc * 4];
                float av[4] = {a.x, a.y, a.z, a.w};
                float bv[4] = {b.x, b.y, b.z, b.w};
#pragma unroll
                for (int i = 0; i < 4; i++)
#pragma unroll
                    for (int j = 0; j < 4; j++) acc[i][j] += av[i] * bv[j];
            }
            __syncthreads();
        }
#pragma unroll
        for (int i = 0; i < 4; i++) {
            size_t base = (size_t)(row0 + tr * 4 + i) * DOUT + col0 + tc * 4;
            float4 v = make_float4(acc[i][0], acc[i][1], acc[i][2], acc[i][3]);
            *(float4*)(C + base) = v;
            __half2 h0 = __floats2half2_rn(acc[i][0], acc[i][1]);
            __half2 h1 = __floats2half2_rn(acc[i][2], acc[i][3]);
            __half2* dh = (__half2*)(Ch + base);
            dh[0] = h0;
            dh[1] = h1;
        }
    } else {
        // ---------------- compaction path: one half-row, one load round ------
        int cid  = grp * 32 + (r - 3);  // 0..8191
        int n    = cid >> 1;
        int half = cid & 1;
        int lane = tx & 31;
        int wid = tx >> 5;

        const int4* pa0 = (const int4*)(atten + ((size_t)0 * NN + n) * NN);
        const int4* pa1 = (const int4*)(atten + ((size_t)1 * NN + n) * NN);
        const int4* pa2 = (const int4*)(atten + ((size_t)2 * NN + n) * NN);
        const int4* ps0 = (const int4*)(supports + ((size_t)0 * NN + n) * NN);
        const int4* ps1 = (const int4*)(supports + ((size_t)1 * NN + n) * NN);
        const int4* ps2 = (const int4*)(supports + ((size_t)2 * NN + n) * NN);

        int i0 = half * 512 + tx;      // int4 index; second batch at +256

        // front-batched 12 loads (MLP_p1 = 12)
        int4 A0 = __ldcs(pa0 + i0);
        int4 A1 = __ldcs(pa1 + i0);
        int4 A2 = __ldcs(pa2 + i0);
        int4 S0 = __ldcs(ps0 + i0);
        int4 S1 = __ldcs(ps1 + i0);
        int4 S2 = __ldcs(ps2 + i0);
        int4 B0 = __ldcs(pa0 + i0 + 256);
        int4 B1 = __ldcs(pa1 + i0 + 256);
        int4 B2 = __ldcs(pa2 + i0 + 256);
        int4 T0 = __ldcs(ps0 + i0 + 256);
        int4 T1 = __ldcs(ps1 + i0 + 256);
        int4 T2 = __ldcs(ps2 + i0 + 256);

        unsigned char codes[8];
        int cnt_local = 0;
        {
            int aa0[4] = {A0.x, A0.y, A0.z, A0.w};
            int aa1[4] = {A1.x, A1.y, A1.z, A1.w};
            int aa2[4] = {A2.x, A2.y, A2.z, A2.w};
            int qq0[4] = {S0.x, S0.y, S0.z, S0.w};
            int qq1[4] = {S1.x, S1.y, S1.z, S1.w};
            int qq2[4] = {S2.x, S2.y, S2.z, S2.w};
#pragma unroll
            for (int j = 0; j < 4; j++) {
                int code = (aa0[j] ? 1 : 0) | (aa1[j] ? 2 : 0) | (aa2[j] ? 4 : 0) |
                           (qq0[j] ? 8 : 0) | (qq1[j] ? 16 : 0) | (qq2[j] ? 32 : 0);
                codes[j] = (unsigned char)code;
                cnt_local += (code != 0);
            }
        }
        {
            int aa0[4] = {B0.x, B0.y, B0.z, B0.w};
            int aa1[4] = {B1.x, B1.y, B1.z, B1.w};
            int aa2[4] = {B2.x, B2.y, B2.z, B2.w};
            int qq0[4] = {T0.x, T0.y, T0.z, T0.w};
            int qq1[4] = {T1.x, T1.y, T1.z, T1.w};
            int qq2[4] = {T2.x, T2.y, T2.z, T2.w};
#pragma unroll
            for (int j = 0; j < 4; j++) {
                int code = (aa0[j] ? 1 : 0) | (aa1[j] ? 2 : 0) | (aa2[j] ? 4 : 0) |
                           (qq0[j] ? 8 : 0) | (qq1[j] ? 16 : 0) | (qq2[j] ? 32 : 0);
                codes[4 + j] = (unsigned char)code;
                cnt_local += (code != 0);
            }
        }

        int incl = cnt_local;
#pragma unroll
        for (int o = 1; o < 32; o <<= 1) {
            int t = __shfl_up_sync(0xffffffffu, incl, o);
            if (lane >= o) incl += t;
        }
        if (lane == 31) s_warp[wid] = incl;
        __syncthreads();
        if (tx < 8) {
            int t = s_warp[tx];
            int p = t;
#pragma unroll
            for (int o = 1; o < 8; o <<= 1) {
                int u = __shfl_up_sync(0xffu, p, o);
                if (tx >= o) p += u;
            }
            s_warp[tx] = p - t;
        }
        __syncthreads();
        int off = s_warp[wid] + incl - cnt_local;
        if (tx == 255) g_cnt[cid] = min(off + cnt_local, CAPH);

        unsigned* lst = g_list + (size_t)n * CAP + half * CAPH;
#pragma unroll
        for (int s = 0; s < 2; s++) {
#pragma unroll
            for (int j = 0; j < 4; j++) {
                int c = codes[s * 4 + j];
                if (c) {
                    int m = (i0 + s * 256) * 4 + j;
                    if (off < CAPH) lst[off] = ((unsigned)m << 6) | (unsigned)c;
                    off++;
                }
            }
        }
    }
}

// ---------------------------------------------------------------------------
// Kernel B: al / ar projections
// ---------------------------------------------------------------------------
__global__ void alar_kernel(const float* __restrict__ Wl,
                            const float* __restrict__ Wr) {
    int k = blockIdx.y;
    int n0 = blockIdx.x * 32;
    __shared__ float sx[32][DOUT + 1];

    const float* wx = g_wx + (size_t)k * NN * DOUT;
    for (int i = threadIdx.x; i < 32 * (DOUT / 4); i += blockDim.x) {
        int rr = i / (DOUT / 4);
        int c = i % (DOUT / 4);
        float4 v = *(const float4*)(wx + (size_t)(n0 + rr) * DOUT + c * 4);
        sx[rr][c * 4 + 0] = v.x;
        sx[rr][c * 4 + 1] = v.y;
        sx[rr][c * 4 + 2] = v.z;
        sx[rr][c * 4 + 3] = v.w;
    }
    __syncthreads();

    int n = threadIdx.x >> 3;
    int j = threadIdx.x & 7;
    const float* w = (j < 4) ? (Wl + (size_t)(k * 4 + j) * DOUT)
                             : (Wr + (size_t)(k * 4 + (j - 4)) * DOUT);
    float s = 0.f;
#pragma unroll 8
    for (int d = 0; d < DOUT; d++) s += sx[n][d] * w[d];

    if (j < 4)
        g_al[((size_t)k * NN + n0 + n) * 4 + j] = s;
    else
        g_ar[((size_t)k * NN + n0 + n) * 4 + (j - 4)] = s;
}

// ---------------------------------------------------------------------------
// Kernel C: per-row attention; dense per-k (m, p/sum) lists, contiguous gather
// ---------------------------------------------------------------------------
__global__ void __launch_bounds__(256)
attn_kernel(float* __restrict__ out) {
    int n = blockIdx.x;
    int tid = threadIdx.x;
    int lane = tid & 31;
    int wid = tid >> 5;

    __shared__ unsigned s_list[CAP];
    __shared__ float s_p[3][CAP];                 // aliased by s_part after ph3
    __shared__ unsigned short s_mk[3 * CAP];
    __shared__ float s_pv[3 * CAP];
    __shared__ float s_al[3][4];
    __shared__ float s_red[3][8];
    __shared__ float s_mx[3];
    __shared__ float s_inv[3];
    __shared__ int s_warp[8];
    __shared__ int s_tot;

    float (*s_part)[128][2] = (float (*)[128][2])s_p;   // 2KB alias into s_p

    if (tid < 12) {
        int k = tid >> 2, j = tid & 3;
        s_al[k][j] = g_al[((size_t)k * NN + n) * 4 + j];
    }

    int c0 = g_cnt[2 * n];
    int c1 = g_cnt[2 * n + 1];
    int cnt = c0 + c1;
    const unsigned* l0 = g_list + (size_t)n * CAP;
    const unsigned* l1 = l0 + CAPH;
    for (int e = tid; e < c0; e += 256) s_list[e] = l0[e];
    for (int e = tid; e < c1; e += 256) s_list[c0 + e] = l1[e];
    __syncthreads();

    // ---- phase 1: scores for all 3 k, track running max
    float mx[3] = {-INFINITY, -INFINITY, -INFINITY};
    for (int e = tid; e < cnt; e += 256) {
        unsigned v = s_list[e];
        int m = (int)(v >> 6);
        int code = (int)(v & 63u);
#pragma unroll
        for (int k = 0; k < 3; k++) {
            float4 arv = *(const float4*)(g_ar + ((size_t)k * NN + m) * 4);
            float s = 0.f;
            if (code & 1) s += s_al[k][0] + arv.x;
            if (code & 2) s += s_al[k][1] + arv.y;
            if (code & 4) s += s_al[k][2] + arv.z;
            if (code & (8 << k)) s += s_al[k][3] + arv.w;
            s_p[k][e] = s;
            if (s != 0.f) mx[k] = fmaxf(mx[k], s);
        }
    }
#pragma unroll
    for (int k = 0; k < 3; k++)
#pragma unroll
        for (int o = 16; o; o >>= 1)
            mx[k] = fmaxf(mx[k], __shfl_xor_sync(0xffffffffu, mx[k], o));
    if (lane == 0) {
#pragma unroll
        for (int k = 0; k < 3; k++) s_red[k][wid] = mx[k];
    }
    __syncthreads();
    if (tid == 0) {
#pragma unroll
        for (int k = 0; k < 3; k++) {
            float m = s_red[k][0];
#pragma unroll
            for (int w = 1; w < 8; w++) m = fmaxf(m, s_red[k][w]);
            s_mx[k] = m;
        }
    }
    __syncthreads();

    // ---- phase 2: exp + sum + per-k valid counts
    float mxk[3] = {s_mx[0], s_mx[1], s_mx[2]};
    float sm[3] = {0.f, 0.f, 0.f};
    int ck[3] = {0, 0, 0};
    for (int e = tid; e < cnt; e += 256) {
#pragma unroll
        for (int k = 0; k < 3; k++) {
            float s = s_p[k][e];
            float p = (s != 0.f) ? __expf(s - mxk[k]) : 0.f;
            s_p[k][e] = p;
            sm[k] += p;
            ck[k] += (p != 0.f);
        }
    }
#pragma unroll
    for (int k = 0; k < 3; k++)
#pragma unroll
        for (int o = 16; o; o >>= 1)
            sm[k] += __shfl_xor_sync(0xffffffffu, sm[k], o);
    if (lane == 0) {
#pragma unroll
        for (int k = 0; k < 3; k++) s_red[k][wid] = sm[k];
    }

    // packed prefix sum of per-k counts (10 bits each)
    int packed = ck[0] | (ck[1] << 10) | (ck[2] << 20);
    int incl = packed;
#pragma unroll
    for (int o = 1; o < 32; o <<= 1) {
        int t = __shfl_up_sync(0xffffffffu, incl, o);
        if (lane >= o) incl += t;
    }
    if (lane == 31) s_warp[wid] = incl;
    __syncthreads();
    if (tid == 0) {
#pragma unroll
        for (int k = 0; k < 3; k++) {
            float t = 0.f;
#pragma unroll
            for (int w = 0; w < 8; w++) t += s_red[k][w];
            s_inv[k] = (t > 0.f) ? (1.0f / t) : 0.f;
        }
    }
    if (tid < 8) {
        int t = s_warp[tid];
        int p = t;
#pragma unroll
        for (int o = 1; o < 8; o <<= 1) {
            int u = __shfl_up_sync(0xffu, p, o);
            if (tid >= o) p += u;
        }
        s_warp[tid] = p - t;
        if (tid == 7) s_tot = p;
    }
    __syncthreads();

    int tot_packed = s_tot;
    int tot0 = tot_packed & 1023;
    int tot1 = (tot_packed >> 10) & 1023;
    int tot2 = (tot_packed >> 20) & 1023;
    int base_k[3];
    base_k[0] = 0;
    base_k[1] = tot0;
    base_k[2] = tot0 + tot1;

    int excl = s_warp[wid] + incl - packed;
    int offk[3];
    offk[0] = base_k[0] + (excl & 1023);
    offk[1] = base_k[1] + ((excl >> 10) & 1023);
    offk[2] = base_k[2] + ((excl >> 20) & 1023);

    // ---- phase 3: write dense (m, p/sum) lists
    float invk[3] = {s_inv[0], s_inv[1], s_inv[2]};
    for (int e = tid; e < cnt; e += 256) {
        unsigned m = s_list[e] >> 6;
#pragma unroll
        for (int k = 0; k < 3; k++) {
            float p = s_p[k][e];
            if (p != 0.f) {
                s_mk[offk[k]] = (unsigned short)m;
                s_pv[offk[k]] = p * invk[k];
                offk[k]++;
            }
        }
    }
    __syncthreads();   // s_p dead from here; s_part may alias

    // ---- phase 4: contiguous branch-free gather over dense lists
    int half_idx = tid >> 7;        // 0 or 1
    int l128 = tid & 127;           // half2 channel index
    const __half2* wxh = (const __half2*)g_wxh;

    float a0 = 0.f, a1 = 0.f;
    int totk[3] = {tot0, tot1, tot2};
#pragma unroll
    for (int k = 0; k < 3; k++) {
        const __half2* plane = wxh + (size_t)k * NN * (DOUT / 2) + l128;
        int b = base_k[k];
        int t = totk[k];
        int sfirst = (t + 1) >> 1;
        int lo = half_idx ? sfirst : 0;
        int hi = half_idx ? t : sfirst;
#pragma unroll 8
        for (int e = lo; e < hi; e++) {
            float p = s_pv[b + e];
            int m = s_mk[b + e];
            float2 f = __half22float2(plane[(size_t)m << 7]);
            a0 += p * f.x;
            a1 += p * f.y;
        }
    }
    s_part[half_idx][l128][0] = a0;
    s_part[half_idx][l128][1] = a1;
    __syncthreads();

    if (tid < 128) {
        float t0 = s_part[0][tid][0] + s_part[1][tid][0];
        float t1 = s_part[0][tid][1] + s_part[1][tid][1];
        float o0 = (t0 > 0.f) ? t0 : expm1f(t0);
        float o1 = (t1 > 0.f) ? t1 : expm1f(t1);
        *(float2*)(out + (size_t)n * DOUT + tid * 2) = make_float2(o0, o1);
    }
}

// ---------------------------------------------------------------------------
extern "C" void kernel_launch(void* const* d_in, const int* in_sizes, int n_in,
                              void* d_out, int out_size) {
    const float* x        = (const float*)d_in[0];
    const int*   supports = (const int*)d_in[1];
    const int*   atten    = (const int*)d_in[2];
    const float* Wt       = (const float*)d_in[3];
    const float* Wl       = (const float*)d_in[4];
    const float* Wr       = (const float*)d_in[5];
    float* out = (float*)d_out;

    fused_gemm_compact<<<TOTAL_BLOCKS, 256>>>(x, Wt, supports, atten);

    dim3 g2(NN / 32, KH);
    alar_kernel<<<g2, 256>>>(Wl, Wr);

    attn_kernel<<<NN, 256>>>(out);
}

// round 6
// speedup vs baseline: 1.0052x; 1.0052x over previous
#include <cuda_runtime.h>
#include <cuda_fp16.h>
#include <math.h>

#define NN 4096
#define DIN 256
#define DOUT 256
#define KH 3
#define CAP 384
#define GEMM_BLOCKS 768
#define TOTAL_BLOCKS 8960     // 256 groups * 35 (3 gemm + 32 code-scan)

// scratch (device globals: no allocation allowed)
__device__ float  g_wx[KH * NN * DOUT];          // 12 MB fp32 (for alar)
__device__ __half g_wxh[KH * NN * DOUT];         // 6 MB fp16 (for gather)
__device__ float  g_al[KH * NN * 4];
__device__ float  g_ar[KH * NN * 4];
__device__ unsigned g_code[NN * 1024];           // 16 MB: 1 code byte per (n,m)

// ---------------------------------------------------------------------------
// Kernel A: fused GEMM + mask->code streaming scan (no smem/barriers in scan)
// ---------------------------------------------------------------------------
__global__ void __launch_bounds__(256)
fused_gemm_scan(const float* __restrict__ x,
                const float* __restrict__ Wt,
                const int* __restrict__ supports,
                const int* __restrict__ atten) {
    __shared__ float As[16][64];
    __shared__ float Bs[16][64];

    int bid = blockIdx.x;               // 0 .. 8959
    int grp = bid / 35;
    int r   = bid % 35;
    int tx  = threadIdx.x;

    if (r < 3) {
        // ---------------- GEMM path ----------------
        int gid = grp * 3 + r;          // 0..767
        int k = gid >> 8;
        int rem = gid & 255;
        int row0 = (rem >> 2) * 64;
        int col0 = (rem & 3) * 64;
        const float* B = Wt + (size_t)k * DIN * DOUT;
        float*  C  = g_wx  + (size_t)k * NN * DOUT;
        __half* Ch = g_wxh + (size_t)k * NN * DOUT;

        int tr = tx >> 4;
        int tc = tx & 15;

        float acc[4][4];
#pragma unroll
        for (int i = 0; i < 4; i++)
#pragma unroll
            for (int j = 0; j < 4; j++) acc[i][j] = 0.f;

        for (int kk = 0; kk < DIN; kk += 16) {
            {
                int rr = tx >> 2;
                int c4 = (tx & 3) * 4;
                float4 v = *(const float4*)(x + (size_t)(row0 + rr) * DIN + kk + c4);
                As[c4 + 0][rr] = v.x;
                As[c4 + 1][rr] = v.y;
                As[c4 + 2][rr] = v.z;
                As[c4 + 3][rr] = v.w;
            }
            {
                int rr = tx >> 4;
                int cc = tx & 15;
                float4 w = *(const float4*)(B + (size_t)(kk + rr) * DOUT + col0 + cc * 4);
                *(float4*)&Bs[rr][cc * 4] = w;
            }
            __syncthreads();
#pragma unroll
            for (int p = 0; p < 16; p++) {
                float4 a = *(float4*)&As[p][tr * 4];
                float4 b = *(float4*)&Bs[p][tc * 4];
                float av[4] = {a.x, a.y, a.z, a.w};
                float bv[4] = {b.x, b.y, b.z, b.w};
#pragma unroll
                for (int i = 0; i < 4; i++)
#pragma unroll
                    for (int j = 0; j < 4; j++) acc[i][j] += av[i] * bv[j];
            }
            __syncthreads();
        }
#pragma unroll
        for (int i = 0; i < 4; i++) {
            size_t base = (size_t)(row0 + tr * 4 + i) * DOUT + col0 + tc * 4;
            float4 v = make_float4(acc[i][0], acc[i][1], acc[i][2], acc[i][3]);
            *(float4*)(C + base) = v;
            __half2 h0 = __floats2half2_rn(acc[i][0], acc[i][1]);
            __half2 h1 = __floats2half2_rn(acc[i][2], acc[i][3]);
            __half2* dh = (__half2*)(Ch + base);
            dh[0] = h0;
            dh[1] = h1;
        }
    } else {
        // ---------------- streaming scan path: masks -> code bytes ----------
        int cid  = grp * 32 + (r - 3);  // 0..8191 (half-row)
        int n    = cid >> 1;
        int half = cid & 1;

        const int4* pa0 = (const int4*)(atten + ((size_t)0 * NN + n) * NN);
        const int4* pa1 = (const int4*)(atten + ((size_t)1 * NN + n) * NN);
        const int4* pa2 = (const int4*)(atten + ((size_t)2 * NN + n) * NN);
        const int4* ps0 = (const int4*)(supports + ((size_t)0 * NN + n) * NN);
        const int4* ps1 = (const int4*)(supports + ((size_t)1 * NN + n) * NN);
        const int4* ps2 = (const int4*)(supports + ((size_t)2 * NN + n) * NN);

        unsigned* crow = g_code + (size_t)n * 1024;

#pragma unroll
        for (int s = 0; s < 2; s++) {
            int i = half * 512 + s * 256 + tx;     // u32/int4 index in row
            int4 a0 = __ldcs(pa0 + i);
            int4 a1 = __ldcs(pa1 + i);
            int4 a2 = __ldcs(pa2 + i);
            int4 q0 = __ldcs(ps0 + i);
            int4 q1 = __ldcs(ps1 + i);
            int4 q2 = __ldcs(ps2 + i);
            int aa0[4] = {a0.x, a0.y, a0.z, a0.w};
            int aa1[4] = {a1.x, a1.y, a1.z, a1.w};
            int aa2[4] = {a2.x, a2.y, a2.z, a2.w};
            int qq0[4] = {q0.x, q0.y, q0.z, q0.w};
            int qq1[4] = {q1.x, q1.y, q1.z, q1.w};
            int qq2[4] = {q2.x, q2.y, q2.z, q2.w};
            unsigned w = 0;
#pragma unroll
            for (int j = 0; j < 4; j++) {
                unsigned code = (aa0[j] ? 1u : 0u) | (aa1[j] ? 2u : 0u) |
                                (aa2[j] ? 4u : 0u) | (qq0[j] ? 8u : 0u) |
                                (qq1[j] ? 16u : 0u) | (qq2[j] ? 32u : 0u);
                w |= code << (8 * j);
            }
            __stcs(crow + i, w);
        }
    }
}

// ---------------------------------------------------------------------------
// Kernel B: al / ar projections
// ---------------------------------------------------------------------------
__global__ void alar_kernel(const float* __restrict__ Wl,
                            const float* __restrict__ Wr) {
    int k = blockIdx.y;
    int n0 = blockIdx.x * 32;
    __shared__ float sx[32][DOUT + 1];

    const float* wx = g_wx + (size_t)k * NN * DOUT;
    for (int i = threadIdx.x; i < 32 * (DOUT / 4); i += blockDim.x) {
        int rr = i / (DOUT / 4);
        int c = i % (DOUT / 4);
        float4 v = *(const float4*)(wx + (size_t)(n0 + rr) * DOUT + c * 4);
        sx[rr][c * 4 + 0] = v.x;
        sx[rr][c * 4 + 1] = v.y;
        sx[rr][c * 4 + 2] = v.z;
        sx[rr][c * 4 + 3] = v.w;
    }
    __syncthreads();

    int n = threadIdx.x >> 3;
    int j = threadIdx.x & 7;
    const float* w = (j < 4) ? (Wl + (size_t)(k * 4 + j) * DOUT)
                             : (Wr + (size_t)(k * 4 + (j - 4)) * DOUT);
    float s = 0.f;
#pragma unroll 8
    for (int d = 0; d < DOUT; d++) s += sx[n][d] * w[d];

    if (j < 4)
        g_al[((size_t)k * NN + n0 + n) * 4 + j] = s;
    else
        g_ar[((size_t)k * NN + n0 + n) * 4 + (j - 4)] = s;
}

// ---------------------------------------------------------------------------
// Kernel C: per-row attention; decodes code row, compacts in-block, then
// dense per-k (m, p/sum) lists and contiguous branch-free fp16 gather.
// ---------------------------------------------------------------------------
__global__ void __launch_bounds__(256)
attn_kernel(float* __restrict__ out) {
    int n = blockIdx.x;
    int tid = threadIdx.x;
    int lane = tid & 31;
    int wid = tid >> 5;

    __shared__ unsigned s_list[CAP];
    __shared__ float s_p[3][CAP];                 // aliased by s_part after ph3
    __shared__ unsigned short s_mk[3 * CAP];
    __shared__ float s_pv[3 * CAP];
    __shared__ float s_al[3][4];
    __shared__ float s_red[3][8];
    __shared__ float s_mx[3];
    __shared__ float s_inv[3];
    __shared__ int s_warp[8];
    __shared__ int s_tot;
    __shared__ int s_cnt;

    float (*s_part)[128][2] = (float (*)[128][2])s_p;   // 2KB alias into s_p

    if (tid < 12) {
        int k = tid >> 2, j = tid & 3;
        s_al[k][j] = g_al[((size_t)k * NN + n) * 4 + j];
    }

    // ---- phase 0: decode code row + in-block compaction (ascending m)
    int4 cw = ((const int4*)(g_code + (size_t)n * 1024))[tid];  // elems 16t..16t+15
    unsigned w4[4] = {(unsigned)cw.x, (unsigned)cw.y, (unsigned)cw.z, (unsigned)cw.w};
    int cnt_local = 0;
#pragma unroll
    for (int q = 0; q < 4; q++)
        cnt_local += __popc(__vcmpne4(w4[q], 0u)) >> 3;

    {
        int incl = cnt_local;
#pragma unroll
        for (int o = 1; o < 32; o <<= 1) {
            int t = __shfl_up_sync(0xffffffffu, incl, o);
            if (lane >= o) incl += t;
        }
        if (lane == 31) s_warp[wid] = incl;
        __syncthreads();
        if (tid < 8) {
            int t = s_warp[tid];
            int p = t;
#pragma unroll
            for (int o = 1; o < 8; o <<= 1) {
                int u = __shfl_up_sync(0xffu, p, o);
                if (tid >= o) p += u;
            }
            s_warp[tid] = p - t;
            if (tid == 7) s_cnt = p;
        }
        __syncthreads();
        int off = s_warp[wid] + incl - cnt_local;
#pragma unroll
        for (int q = 0; q < 4; q++) {
#pragma unroll
            for (int j = 0; j < 4; j++) {
                unsigned c = (w4[q] >> (8 * j)) & 255u;
                if (c) {
                    unsigned m = (unsigned)(tid * 16 + q * 4 + j);
                    if (off < CAP) s_list[off] = (m << 6) | c;
                    off++;
                }
            }
        }
    }
    __syncthreads();
    int cnt = min(s_cnt, CAP);

    // ---- phase 1: scores for all 3 k, track running max
    float mx[3] = {-INFINITY, -INFINITY, -INFINITY};
    for (int e = tid; e < cnt; e += 256) {
        unsigned v = s_list[e];
        int m = (int)(v >> 6);
        int code = (int)(v & 63u);
#pragma unroll
        for (int k = 0; k < 3; k++) {
            float4 arv = *(const float4*)(g_ar + ((size_t)k * NN + m) * 4);
            float s = 0.f;
            if (code & 1) s += s_al[k][0] + arv.x;
            if (code & 2) s += s_al[k][1] + arv.y;
            if (code & 4) s += s_al[k][2] + arv.z;
            if (code & (8 << k)) s += s_al[k][3] + arv.w;
            s_p[k][e] = s;
            if (s != 0.f) mx[k] = fmaxf(mx[k], s);
        }
    }
#pragma unroll
    for (int k = 0; k < 3; k++)
#pragma unroll
        for (int o = 16; o; o >>= 1)
            mx[k] = fmaxf(mx[k], __shfl_xor_sync(0xffffffffu, mx[k], o));
    if (lane == 0) {
#pragma unroll
        for (int k = 0; k < 3; k++) s_red[k][wid] = mx[k];
    }
    __syncthreads();
    if (tid == 0) {
#pragma unroll
        for (int k = 0; k < 3; k++) {
            float m = s_red[k][0];
#pragma unroll
            for (int w = 1; w < 8; w++) m = fmaxf(m, s_red[k][w]);
            s_mx[k] = m;
        }
    }
    __syncthreads();

    // ---- phase 2: exp + sum + per-k valid counts
    float mxk[3] = {s_mx[0], s_mx[1], s_mx[2]};
    float sm[3] = {0.f, 0.f, 0.f};
    int ck[3] = {0, 0, 0};
    for (int e = tid; e < cnt; e += 256) {
#pragma unroll
        for (int k = 0; k < 3; k++) {
            float s = s_p[k][e];
            float p = (s != 0.f) ? __expf(s - mxk[k]) : 0.f;
            s_p[k][e] = p;
            sm[k] += p;
            ck[k] += (p != 0.f);
        }
    }
#pragma unroll
    for (int k = 0; k < 3; k++)
#pragma unroll
        for (int o = 16; o; o >>= 1)
            sm[k] += __shfl_xor_sync(0xffffffffu, sm[k], o);
    if (lane == 0) {
#pragma unroll
        for (int k = 0; k < 3; k++) s_red[k][wid] = sm[k];
    }

    // packed prefix sum of per-k counts (10 bits each)
    int packed = ck[0] | (ck[1] << 10) | (ck[2] << 20);
    int incl = packed;
#pragma unroll
    for (int o = 1; o < 32; o <<= 1) {
        int t = __shfl_up_sync(0xffffffffu, incl, o);
        if (lane >= o) incl += t;
    }
    if (lane == 31) s_warp[wid] = incl;
    __syncthreads();
    if (tid == 0) {
#pragma unroll
        for (int k = 0; k < 3; k++) {
            float t = 0.f;
#pragma unroll
            for (int w = 0; w < 8; w++) t += s_red[k][w];
            s_inv[k] = (t > 0.f) ? (1.0f / t) : 0.f;
        }
    }
    if (tid < 8) {
        int t = s_warp[tid];
        int p = t;
#pragma unroll
        for (int o = 1; o < 8; o <<= 1) {
            int u = __shfl_up_sync(0xffu, p, o);
            if (tid >= o) p += u;
        }
        s_warp[tid] = p - t;
        if (tid == 7) s_tot = p;
    }
    __syncthreads();

    int tot_packed = s_tot;
    int tot0 = tot_packed & 1023;
    int tot1 = (tot_packed >> 10) & 1023;
    int tot2 = (tot_packed >> 20) & 1023;
    int base_k[3];
    base_k[0] = 0;
    base_k[1] = tot0;
    base_k[2] = tot0 + tot1;

    int excl = s_warp[wid] + incl - packed;
    int offk[3];
    offk[0] = base_k[0] + (excl & 1023);
    offk[1] = base_k[1] + ((excl >> 10) & 1023);
    offk[2] = base_k[2] + ((excl >> 20) & 1023);

    // ---- phase 3: write dense (m, p/sum) lists
    float invk[3] = {s_inv[0], s_inv[1], s_inv[2]};
    for (int e = tid; e < cnt; e += 256) {
        unsigned m = s_list[e] >> 6;
#pragma unroll
        for (int k = 0; k < 3; k++) {
            float p = s_p[k][e];
            if (p != 0.f) {
                s_mk[offk[k]] = (unsigned short)m;
                s_pv[offk[k]] = p * invk[k];
                offk[k]++;
            }
        }
    }
    __syncthreads();   // s_p dead from here; s_part may alias

    // ---- phase 4: contiguous branch-free gather over dense lists
    int half_idx = tid >> 7;        // 0 or 1
    int l128 = tid & 127;           // half2 channel index
    const __half2* wxh = (const __half2*)g_wxh;

    float a0 = 0.f, a1 = 0.f;
    int totk[3] = {tot0, tot1, tot2};
#pragma unroll
    for (int k = 0; k < 3; k++) {
        const __half2* plane = wxh + (size_t)k * NN * (DOUT / 2) + l128;
        int b = base_k[k];
        int t = totk[k];
        int sfirst = (t + 1) >> 1;
        int lo = half_idx ? sfirst : 0;
        int hi = half_idx ? t : sfirst;
#pragma unroll 8
        for (int e = lo; e < hi; e++) {
            float p = s_pv[b + e];
            int m = s_mk[b + e];
            float2 f = __half22float2(plane[(size_t)m << 7]);
            a0 += p * f.x;
            a1 += p * f.y;
        }
    }
    s_part[half_idx][l128][0] = a0;
    s_part[half_idx][l128][1] = a1;
    __syncthreads();

    if (tid < 128) {
        float t0 = s_part[0][tid][0] + s_part[1][tid][0];
        float t1 = s_part[0][tid][1] + s_part[1][tid][1];
        float o0 = (t0 > 0.f) ? t0 : expm1f(t0);
        float o1 = (t1 > 0.f) ? t1 : expm1f(t1);
        *(float2*)(out + (size_t)n * DOUT + tid * 2) = make_float2(o0, o1);
    }
}

// ---------------------------------------------------------------------------
extern "C" void kernel_launch(void* const* d_in, const int* in_sizes, int n_in,
                              void* d_out, int out_size) {
    const float* x        = (const float*)d_in[0];
    const int*   supports = (const int*)d_in[1];
    const int*   atten    = (const int*)d_in[2];
    const float* Wt       = (const float*)d_in[3];
    const float* Wl       = (const float*)d_in[4];
    const float* Wr       = (const float*)d_in[5];
    float* out = (float*)d_out;

    fused_gemm_scan<<<TOTAL_BLOCKS, 256>>>(x, Wt, supports, atten);

    dim3 g2(NN / 32, KH);
    alar_kernel<<<g2, 256>>>(Wl, Wr);

    attn_kernel<<<NN, 256>>>(out);
}

// round 7
// speedup vs baseline: 1.1180x; 1.1122x over previous
#include <cuda_runtime.h>
#include <cuda_fp16.h>
#include <math.h>

#define NN 4096
#define DIN 256
#define DOUT 256
#define KH 3
#define CAP 384
#define GEMM_BLOCKS 768
#define TOTAL_BLOCKS 8960     // 256 groups * 35 (3 gemm + 32 code-scan)

// scratch (device globals: no allocation allowed)
__device__ float  g_wx[KH * NN * DOUT];          // 12 MB fp32 (for alar)
__device__ __half g_wxh[KH * NN * DOUT];         // 6 MB fp16 (for gather)
__device__ float  g_al[KH * NN * 4];
__device__ float  g_ar[KH * NN * 4];
__device__ unsigned g_code[NN * 1024];           // 16 MB: 1 code byte per (n,m)

// ---------------------------------------------------------------------------
// Kernel A: fused GEMM + mask->code streaming scan (unchanged from R6)
// ---------------------------------------------------------------------------
__global__ void __launch_bounds__(256)
fused_gemm_scan(const float* __restrict__ x,
                const float* __restrict__ Wt,
                const int* __restrict__ supports,
                const int* __restrict__ atten) {
    __shared__ float As[16][64];
    __shared__ float Bs[16][64];

    int bid = blockIdx.x;               // 0 .. 8959
    int grp = bid / 35;
    int r   = bid % 35;
    int tx  = threadIdx.x;

    if (r < 3) {
        // ---------------- GEMM path ----------------
        int gid = grp * 3 + r;          // 0..767
        int k = gid >> 8;
        int rem = gid & 255;
        int row0 = (rem >> 2) * 64;
        int col0 = (rem & 3) * 64;
        const float* B = Wt + (size_t)k * DIN * DOUT;
        float*  C  = g_wx  + (size_t)k * NN * DOUT;
        __half* Ch = g_wxh + (size_t)k * NN * DOUT;

        int tr = tx >> 4;
        int tc = tx & 15;

        float acc[4][4];
#pragma unroll
        for (int i = 0; i < 4; i++)
#pragma unroll
            for (int j = 0; j < 4; j++) acc[i][j] = 0.f;

        for (int kk = 0; kk < DIN; kk += 16) {
            {
                int rr = tx >> 2;
                int c4 = (tx & 3) * 4;
                float4 v = *(const float4*)(x + (size_t)(row0 + rr) * DIN + kk + c4);
                As[c4 + 0][rr] = v.x;
                As[c4 + 1][rr] = v.y;
                As[c4 + 2][rr] = v.z;
                As[c4 + 3][rr] = v.w;
            }
            {
                int rr = tx >> 4;
                int cc = tx & 15;
                float4 w = *(const float4*)(B + (size_t)(kk + rr) * DOUT + col0 + cc * 4);
                *(float4*)&Bs[rr][cc * 4] = w;
            }
            __syncthreads();
#pragma unroll
            for (int p = 0; p < 16; p++) {
                float4 a = *(float4*)&As[p][tr * 4];
                float4 b = *(float4*)&Bs[p][tc * 4];
                float av[4] = {a.x, a.y, a.z, a.w};
                float bv[4] = {b.x, b.y, b.z, b.w};
#pragma unroll
                for (int i = 0; i < 4; i++)
#pragma unroll
                    for (int j = 0; j < 4; j++) acc[i][j] += av[i] * bv[j];
            }
            __syncthreads();
        }
#pragma unroll
        for (int i = 0; i < 4; i++) {
            size_t base = (size_t)(row0 + tr * 4 + i) * DOUT + col0 + tc * 4;
            float4 v = make_float4(acc[i][0], acc[i][1], acc[i][2], acc[i][3]);
            *(float4*)(C + base) = v;
            __half2 h0 = __floats2half2_rn(acc[i][0], acc[i][1]);
            __half2 h1 = __floats2half2_rn(acc[i][2], acc[i][3]);
            __half2* dh = (__half2*)(Ch + base);
            dh[0] = h0;
            dh[1] = h1;
        }
    } else {
        // ---------------- streaming scan path: masks -> code bytes ----------
        int cid  = grp * 32 + (r - 3);  // 0..8191 (half-row)
        int n    = cid >> 1;
        int half = cid & 1;

        const int4* pa0 = (const int4*)(atten + ((size_t)0 * NN + n) * NN);
        const int4* pa1 = (const int4*)(atten + ((size_t)1 * NN + n) * NN);
        const int4* pa2 = (const int4*)(atten + ((size_t)2 * NN + n) * NN);
        const int4* ps0 = (const int4*)(supports + ((size_t)0 * NN + n) * NN);
        const int4* ps1 = (const int4*)(supports + ((size_t)1 * NN + n) * NN);
        const int4* ps2 = (const int4*)(supports + ((size_t)2 * NN + n) * NN);

        unsigned* crow = g_code + (size_t)n * 1024;

#pragma unroll
        for (int s = 0; s < 2; s++) {
            int i = half * 512 + s * 256 + tx;     // u32/int4 index in row
            int4 a0 = __ldcs(pa0 + i);
            int4 a1 = __ldcs(pa1 + i);
            int4 a2 = __ldcs(pa2 + i);
            int4 q0 = __ldcs(ps0 + i);
            int4 q1 = __ldcs(ps1 + i);
            int4 q2 = __ldcs(ps2 + i);
            int aa0[4] = {a0.x, a0.y, a0.z, a0.w};
            int aa1[4] = {a1.x, a1.y, a1.z, a1.w};
            int aa2[4] = {a2.x, a2.y, a2.z, a2.w};
            int qq0[4] = {q0.x, q0.y, q0.z, q0.w};
            int qq1[4] = {q1.x, q1.y, q1.z, q1.w};
            int qq2[4] = {q2.x, q2.y, q2.z, q2.w};
            unsigned w = 0;
#pragma unroll
            for (int j = 0; j < 4; j++) {
                unsigned code = (aa0[j] ? 1u : 0u) | (aa1[j] ? 2u : 0u) |
                                (aa2[j] ? 4u : 0u) | (qq0[j] ? 8u : 0u) |
                                (qq1[j] ? 16u : 0u) | (qq2[j] ? 32u : 0u);
                w |= code << (8 * j);
            }
            __stcs(crow + i, w);
        }
    }
}

// ---------------------------------------------------------------------------
// Kernel B: al / ar projections (unchanged)
// ---------------------------------------------------------------------------
__global__ void alar_kernel(const float* __restrict__ Wl,
                            const float* __restrict__ Wr) {
    int k = blockIdx.y;
    int n0 = blockIdx.x * 32;
    __shared__ float sx[32][DOUT + 1];

    const float* wx = g_wx + (size_t)k * NN * DOUT;
    for (int i = threadIdx.x; i < 32 * (DOUT / 4); i += blockDim.x) {
        int rr = i / (DOUT / 4);
        int c = i % (DOUT / 4);
        float4 v = *(const float4*)(wx + (size_t)(n0 + rr) * DOUT + c * 4);
        sx[rr][c * 4 + 0] = v.x;
        sx[rr][c * 4 + 1] = v.y;
        sx[rr][c * 4 + 2] = v.z;
        sx[rr][c * 4 + 3] = v.w;
    }
    __syncthreads();

    int n = threadIdx.x >> 3;
    int j = threadIdx.x & 7;
    const float* w = (j < 4) ? (Wl + (size_t)(k * 4 + j) * DOUT)
                             : (Wr + (size_t)(k * 4 + (j - 4)) * DOUT);
    float s = 0.f;
#pragma unroll 8
    for (int d = 0; d < DOUT; d++) s += sx[n][d] * w[d];

    if (j < 4)
        g_al[((size_t)k * NN + n0 + n) * 4 + j] = s;
    else
        g_ar[((size_t)k * NN + n0 + n) * 4 + (j - 4)] = s;
}

// ---------------------------------------------------------------------------
// Kernel C: per-row attention. Decode -> scores -> softmax -> packed (p,off)
// pair list -> warp-per-row LDG.128 gather (one warp loads a full 512B row).
// ---------------------------------------------------------------------------
__global__ void __launch_bounds__(256)
attn_kernel(float* __restrict__ out) {
    int n = blockIdx.x;
    int tid = threadIdx.x;
    int lane = tid & 31;
    int wid = tid >> 5;

    __shared__ unsigned s_list[CAP];
    __shared__ float s_p[3][CAP];
    __shared__ unsigned long long s_pair[3 * CAP];   // aliased as s_acc in ph4
    __shared__ float s_al[3][4];
    __shared__ float s_red[3][8];
    __shared__ float s_mx[3];
    __shared__ float s_inv[3];
    __shared__ int s_warp[8];
    __shared__ int s_tot;
    __shared__ int s_cnt;

    float (*s_acc)[256] = (float (*)[256])s_pair;   // 8KB alias (pair=9.2KB)

    if (tid < 12) {
        int k = tid >> 2, j = tid & 3;
        s_al[k][j] = g_al[((size_t)k * NN + n) * 4 + j];
    }

    // ---- phase 0: decode code row + in-block compaction (ascending m)
    int4 cw = ((const int4*)(g_code + (size_t)n * 1024))[tid];  // elems 16t..16t+15
    unsigned w4[4] = {(unsigned)cw.x, (unsigned)cw.y, (unsigned)cw.z, (unsigned)cw.w};
    int cnt_local = 0;
#pragma unroll
    for (int q = 0; q < 4; q++)
        cnt_local += __popc(__vcmpne4(w4[q], 0u)) >> 3;

    {
        int incl = cnt_local;
#pragma unroll
        for (int o = 1; o < 32; o <<= 1) {
            int t = __shfl_up_sync(0xffffffffu, incl, o);
            if (lane >= o) incl += t;
        }
        if (lane == 31) s_warp[wid] = incl;
        __syncthreads();
        if (tid < 8) {
            int t = s_warp[tid];
            int p = t;
#pragma unroll
            for (int o = 1; o < 8; o <<= 1) {
                int u = __shfl_up_sync(0xffu, p, o);
                if (tid >= o) p += u;
            }
            s_warp[tid] = p - t;
            if (tid == 7) s_cnt = p;
        }
        __syncthreads();
        int off = s_warp[wid] + incl - cnt_local;
#pragma unroll
        for (int q = 0; q < 4; q++) {
#pragma unroll
            for (int j = 0; j < 4; j++) {
                unsigned c = (w4[q] >> (8 * j)) & 255u;
                if (c) {
                    unsigned m = (unsigned)(tid * 16 + q * 4 + j);
                    if (off < CAP) s_list[off] = (m << 6) | c;
                    off++;
                }
            }
        }
    }
    __syncthreads();
    int cnt = min(s_cnt, CAP);

    // ---- phase 1: scores for all 3 k, track running max
    float mx[3] = {-INFINITY, -INFINITY, -INFINITY};
    for (int e = tid; e < cnt; e += 256) {
        unsigned v = s_list[e];
        int m = (int)(v >> 6);
        int code = (int)(v & 63u);
#pragma unroll
        for (int k = 0; k < 3; k++) {
            float4 arv = *(const float4*)(g_ar + ((size_t)k * NN + m) * 4);
            float s = 0.f;
            if (code & 1) s += s_al[k][0] + arv.x;
            if (code & 2) s += s_al[k][1] + arv.y;
            if (code & 4) s += s_al[k][2] + arv.z;
            if (code & (8 << k)) s += s_al[k][3] + arv.w;
            s_p[k][e] = s;
            if (s != 0.f) mx[k] = fmaxf(mx[k], s);
        }
    }
#pragma unroll
    for (int k = 0; k < 3; k++)
#pragma unroll
        for (int o = 16; o; o >>= 1)
            mx[k] = fmaxf(mx[k], __shfl_xor_sync(0xffffffffu, mx[k], o));
    if (lane == 0) {
#pragma unroll
        for (int k = 0; k < 3; k++) s_red[k][wid] = mx[k];
    }
    __syncthreads();
    if (tid == 0) {
#pragma unroll
        for (int k = 0; k < 3; k++) {
            float m = s_red[k][0];
#pragma unroll
            for (int w = 1; w < 8; w++) m = fmaxf(m, s_red[k][w]);
            s_mx[k] = m;
        }
    }
    __syncthreads();

    // ---- phase 2: exp + sum + per-k valid counts
    float mxk[3] = {s_mx[0], s_mx[1], s_mx[2]};
    float sm[3] = {0.f, 0.f, 0.f};
    int ck[3] = {0, 0, 0};
    for (int e = tid; e < cnt; e += 256) {
#pragma unroll
        for (int k = 0; k < 3; k++) {
            float s = s_p[k][e];
            float p = (s != 0.f) ? __expf(s - mxk[k]) : 0.f;
            s_p[k][e] = p;
            sm[k] += p;
            ck[k] += (p != 0.f);
        }
    }
#pragma unroll
    for (int k = 0; k < 3; k++)
#pragma unroll
        for (int o = 16; o; o >>= 1)
            sm[k] += __shfl_xor_sync(0xffffffffu, sm[k], o);
    if (lane == 0) {
#pragma unroll
        for (int k = 0; k < 3; k++) s_red[k][wid] = sm[k];
    }

    // packed prefix sum of per-k counts (10 bits each)
    int packed = ck[0] | (ck[1] << 10) | (ck[2] << 20);
    int incl = packed;
#pragma unroll
    for (int o = 1; o < 32; o <<= 1) {
        int t = __shfl_up_sync(0xffffffffu, incl, o);
        if (lane >= o) incl += t;
    }
    if (lane == 31) s_warp[wid] = incl;
    __syncthreads();
    if (tid == 0) {
#pragma unroll
        for (int k = 0; k < 3; k++) {
            float t = 0.f;
#pragma unroll
            for (int w = 0; w < 8; w++) t += s_red[k][w];
            s_inv[k] = (t > 0.f) ? (1.0f / t) : 0.f;
        }
    }
    if (tid < 8) {
        int t = s_warp[tid];
        int p = t;
#pragma unroll
        for (int o = 1; o < 8; o <<= 1) {
            int u = __shfl_up_sync(0xffu, p, o);
            if (tid >= o) p += u;
        }
        s_warp[tid] = p - t;
        if (tid == 7) s_tot = p;
    }
    __syncthreads();

    int tot_packed = s_tot;
    int tot0 = tot_packed & 1023;
    int tot1 = (tot_packed >> 10) & 1023;
    int tot2 = (tot_packed >> 20) & 1023;
    int base_k[3];
    base_k[0] = 0;
    base_k[1] = tot0;
    base_k[2] = tot0 + tot1;
    int tot = tot0 + tot1 + tot2;

    int excl = s_warp[wid] + incl - packed;
    int offk[3];
    offk[0] = base_k[0] + (excl & 1023);
    offk[1] = base_k[1] + ((excl >> 10) & 1023);
    offk[2] = base_k[2] + ((excl >> 20) & 1023);

    // ---- phase 3: write packed (p/sum, k*NN+m) pair list
    float invk[3] = {s_inv[0], s_inv[1], s_inv[2]};
    for (int e = tid; e < cnt; e += 256) {
        unsigned m = s_list[e] >> 6;
#pragma unroll
        for (int k = 0; k < 3; k++) {
            float p = s_p[k][e];
            if (p != 0.f) {
                unsigned off32 = (unsigned)(k * NN) + m;
                s_pair[offk[k]] =
                    (unsigned long long)__float_as_uint(p * invk[k]) |
                    ((unsigned long long)off32 << 32);
                offk[k]++;
            }
        }
    }
    __syncthreads();

    // ---- phase 4: warp-per-row gather. One LDG.128 per warp covers a full
    // 512B fp16 row; lane owns channels [8*lane, 8*lane+8).
    float a0 = 0.f, a1 = 0.f, a2 = 0.f, a3 = 0.f;
    float a4 = 0.f, a5 = 0.f, a6 = 0.f, a7 = 0.f;
#pragma unroll 4
    for (int i = wid; i < tot; i += 8) {
        unsigned long long pr = s_pair[i];
        float p = __uint_as_float((unsigned)pr);
        unsigned off32 = (unsigned)(pr >> 32);
        const uint4* row = (const uint4*)(g_wxh + ((size_t)off32 << 8));
        uint4 v = row[lane];
        __half2 h0 = *(__half2*)&v.x;
        __half2 h1 = *(__half2*)&v.y;
        __half2 h2 = *(__half2*)&v.z;
        __half2 h3 = *(__half2*)&v.w;
        float2 f0 = __half22float2(h0);
        float2 f1 = __half22float2(h1);
        float2 f2 = __half22float2(h2);
        float2 f3 = __half22float2(h3);
        a0 += p * f0.x; a1 += p * f0.y;
        a2 += p * f1.x; a3 += p * f1.y;
        a4 += p * f2.x; a5 += p * f2.y;
        a6 += p * f3.x; a7 += p * f3.y;
    }
    __syncthreads();   // all pair reads complete before aliasing s_pair

    {
        float* dst = &s_acc[wid][lane * 8];
        *(float4*)dst = make_float4(a0, a1, a2, a3);
        *(float4*)(dst + 4) = make_float4(a4, a5, a6, a7);
    }
    __syncthreads();

    // ---- final: reduce 8 warp partials per channel, ELU, store
    {
        float t = s_acc[0][tid];
#pragma unroll
        for (int w = 1; w < 8; w++) t += s_acc[w][tid];
        float o = (t > 0.f) ? t : expm1f(t);
        out[(size_t)n * DOUT + tid] = o;
    }
}

// ---------------------------------------------------------------------------
extern "C" void kernel_launch(void* const* d_in, const int* in_sizes, int n_in,
                              void* d_out, int out_size) {
    const float* x        = (const float*)d_in[0];
    const int*   supports = (const int*)d_in[1];
    const int*   atten    = (const int*)d_in[2];
    const float* Wt       = (const float*)d_in[3];
    const float* Wl       = (const float*)d_in[4];
    const float* Wr       = (const float*)d_in[5];
    float* out = (float*)d_out;

    fused_gemm_scan<<<TOTAL_BLOCKS, 256>>>(x, Wt, supports, atten);

    dim3 g2(NN / 32, KH);
    alar_kernel<<<g2, 256>>>(Wl, Wr);

    attn_kernel<<<NN, 256>>>(out);
}